// round 2
// baseline (speedup 1.0000x reference)
#include <cuda_runtime.h>
#include <cuda_fp16.h>
#include <cstdint>

// ---------------- problem dims ----------------
#define IN_F   4096
#define OUT_F  11008
#define M_TOT  8192
#define GROUPS 32
#define PACKED 512

// ---------------- GEMM tiling ----------------
#define BLOCK_M 128
#define BLOCK_N 256
#define BLOCK_K 64            // 64 halves = 128B rows
#define STAGES  3
#define NITER   (IN_F / BLOCK_K)   // 64
#define NT      (OUT_F / BLOCK_N)  // 43
#define MT      (M_TOT / BLOCK_M)  // 64

#define A_BYTES (BLOCK_M * 128)            // 16384
#define B_BYTES (BLOCK_N * 128)            // 32768
#define STAGE_BYTES (A_BYTES + B_BYTES)    // 49152
#define SMEM_BYTES (STAGES * STAGE_BYTES)  // 147456

// ---------------- scratch (device globals: allocation-free) ----------------
__device__ __align__(1024) __half g_xh[(size_t)M_TOT * IN_F];
__device__ __align__(1024) __half g_wh[(size_t)OUT_F * IN_F];

// ---------------- PTX helpers ----------------
__device__ __forceinline__ uint32_t smem_u32(const void* p) {
    uint32_t a;
    asm("{ .reg .u64 t; cvta.to.shared.u64 t, %1; cvt.u32.u64 %0, t; }" : "=r"(a) : "l"(p));
    return a;
}

#define CP_ASYNC_CG(smem, gptr) \
    asm volatile("cp.async.cg.shared.global [%0], [%1], 16;" :: "r"(smem), "l"(gptr) : "memory")
#define CP_COMMIT() asm volatile("cp.async.commit_group;" ::: "memory")
#define CP_WAIT2()  asm volatile("cp.async.wait_group 2;" ::: "memory")

#define LDSM_X4(R, addr) \
    asm volatile("ldmatrix.sync.aligned.m8n8.x4.shared.b16 {%0,%1,%2,%3}, [%4];" \
                 : "=r"((R)[0]), "=r"((R)[1]), "=r"((R)[2]), "=r"((R)[3]) : "r"(addr))

#define MMA16816(C, A, B) \
    asm volatile("mma.sync.aligned.m16n8k16.row.col.f32.f16.f16.f32 " \
                 "{%0,%1,%2,%3}, {%4,%5,%6,%7}, {%8,%9}, {%0,%1,%2,%3};" \
                 : "+f"((C)[0]), "+f"((C)[1]), "+f"((C)[2]), "+f"((C)[3]) \
                 : "r"((A)[0]), "r"((A)[1]), "r"((A)[2]), "r"((A)[3]), \
                   "r"((B)[0]), "r"((B)[1]))

// ---------------- kernel 1: x fp32 -> fp16 ----------------
__global__ void convert_x_kernel(const float4* __restrict__ x, uint4* __restrict__ out) {
    int i = blockIdx.x * blockDim.x + threadIdx.x;   // one uint4 = 8 halves
    float4 a = x[2 * i];
    float4 b = x[2 * i + 1];
    __half h[8];
    h[0] = __float2half(a.x); h[1] = __float2half(a.y);
    h[2] = __float2half(a.z); h[3] = __float2half(a.w);
    h[4] = __float2half(b.x); h[5] = __float2half(b.y);
    h[6] = __float2half(b.z); h[7] = __float2half(b.w);
    out[i] = *reinterpret_cast<uint4*>(h);
}

// ---------------- kernel 2: int4 dequant -> fp16 ----------------
__global__ void dequant_w_kernel(const int* __restrict__ wp, const float* __restrict__ scales,
                                 const float* __restrict__ biases, __half* __restrict__ out) {
    int idx = blockIdx.x * blockDim.x + threadIdx.x;  // packed-word index
    uint32_t w = (uint32_t)wp[idx];
    int o  = idx >> 9;          // / PACKED
    int wk = idx & 511;
    int g  = wk >> 4;           // 16 words per 128-feature group
    float s = scales[o * GROUPS + g];
    float b = biases[o * GROUPS + g];
    __half h[8];
#pragma unroll
    for (int j = 0; j < 8; j++) {
        float q = (float)((w >> (4 * j)) & 15u);
        h[j] = __float2half(fmaf(s, q, b));
    }
    *reinterpret_cast<uint4*>(out + (size_t)idx * 8) = *reinterpret_cast<uint4*>(h);
}

// ---------------- kernel 3: pipelined mma.sync fp16 GEMM ----------------
// CTA 128x256x64, 8 warps in 2(M) x 4(N), warp tile 64x64.
// smem rows are 128B (64 halves); swizzle: col16B ^= 16*(row&7).
__global__ void __launch_bounds__(256, 1)
gemm_f16_kernel(const __half* __restrict__ Ag, const __half* __restrict__ Bg,
                const float* __restrict__ bias, float* __restrict__ out) {
    extern __shared__ char smem[];
    const uint32_t sbase = smem_u32(smem);

    const int tid = threadIdx.x;
    const int wid = tid >> 5;
    const int lid = tid & 31;

    const int nt = blockIdx.x % NT;
    const int mt = blockIdx.x / NT;

    const int warp_m = wid >> 2;          // 0..1
    const int warp_n = wid & 3;           // 0..3
    const int m_base = warp_m * 64;
    const int n_base = warp_n * 64;

    // ---- cp.async source/dst precompute ----
    // A: 1024 16B-chunks (128 rows x 8), B: 2048 chunks (256 rows x 8).
    // Thread handles chunks tid + 256*k.
    const __half* Agb = Ag + (size_t)mt * BLOCK_M * IN_F;
    const __half* Bgb = Bg + (size_t)nt * BLOCK_N * IN_F;

    // ---- ldmatrix per-thread precompute ----
    const int r  = lid & 7;      // row-within-8
    const int gq = lid >> 3;     // quad group 0..3
    const uint32_t xorv = r * 16;
    // A x4: rows m_base + mf*16 + r + 8*(gq&1), kbyte = ks*32 + 16*(gq>>1)
    const uint32_t aRowOff = (uint32_t)(m_base + r + 8 * (gq & 1)) * 128;
    const uint32_t aKExtra = 16 * (gq >> 1);
    // B x4: rows n_base + (2*jb + (gq>>1))*8 + r, kbyte = ks*32 + 16*(gq&1)
    const uint32_t bRowOff = (uint32_t)(n_base + r) * 128 + (uint32_t)(gq >> 1) * 1024;
    const uint32_t bKExtra = 16 * (gq & 1);

    float c[4][8][4];
#pragma unroll
    for (int mf = 0; mf < 4; mf++)
#pragma unroll
        for (int nf = 0; nf < 8; nf++)
#pragma unroll
            for (int k = 0; k < 4; k++) c[mf][nf][k] = 0.f;

    // ---- async load of one stage ----
    auto load_stage = [&](int it, int stage) {
        const uint32_t sA = sbase + stage * STAGE_BYTES;
        const uint32_t sB = sA + A_BYTES;
        const int k0 = it * BLOCK_K;
        // A: 1024 chunks / 256 threads = 4
#pragma unroll
        for (int k = 0; k < 4; k++) {
            int i = tid + 256 * k;
            int row = i >> 3, cc = i & 7;
            const __half* gp = Agb + (size_t)row * IN_F + k0 + cc * 8;
            uint32_t sp = sA + row * 128 + ((cc * 16) ^ ((row & 7) * 16));
            CP_ASYNC_CG(sp, gp);
        }
        // B: 2048 chunks / 256 threads = 8
#pragma unroll
        for (int k = 0; k < 8; k++) {
            int i = tid + 256 * k;
            int row = i >> 3, cc = i & 7;
            const __half* gp = Bgb + (size_t)row * IN_F + k0 + cc * 8;
            uint32_t sp = sB + row * 128 + ((cc * 16) ^ ((row & 7) * 16));
            CP_ASYNC_CG(sp, gp);
        }
    };

    // prologue: stages 0,1
    load_stage(0, 0); CP_COMMIT();
    load_stage(1, 1); CP_COMMIT();

    for (int it = 0; it < NITER; it++) {
        if (it + 2 < NITER) load_stage(it + 2, (it + 2) % STAGES);
        CP_COMMIT();
        CP_WAIT2();
        __syncthreads();

        const uint32_t sA = sbase + (it % STAGES) * STAGE_BYTES;
        const uint32_t sB = sA + A_BYTES;

#pragma unroll
        for (int ks = 0; ks < 4; ks++) {
            uint32_t a[4][4];
#pragma unroll
            for (int mf = 0; mf < 4; mf++)
                LDSM_X4(a[mf], sA + aRowOff + mf * 2048 + ((ks * 32 + aKExtra) ^ xorv));
            uint32_t b[4][4];
#pragma unroll
            for (int jb = 0; jb < 4; jb++)
                LDSM_X4(b[jb], sB + bRowOff + jb * 2048 + ((ks * 32 + bKExtra) ^ xorv));
#pragma unroll
            for (int mf = 0; mf < 4; mf++)
#pragma unroll
                for (int nf = 0; nf < 8; nf++)
                    MMA16816(c[mf][nf], a[mf], &b[nf >> 1][(nf & 1) * 2]);
        }
        __syncthreads();
    }

    // ---- epilogue: add bias, store fp32 ----
    const int m_lo = lid >> 2;          // 0..7
    const int n_lo = (lid & 3) * 2;     // 0,2,4,6
    const int n_col0 = nt * BLOCK_N + n_base + n_lo;

    float2 bb[8];
#pragma unroll
    for (int nf = 0; nf < 8; nf++) {
        bb[nf].x = __ldg(bias + n_col0 + nf * 8);
        bb[nf].y = __ldg(bias + n_col0 + nf * 8 + 1);
    }

#pragma unroll
    for (int mf = 0; mf < 4; mf++) {
        size_t m0 = (size_t)mt * BLOCK_M + m_base + mf * 16 + m_lo;
#pragma unroll
        for (int nf = 0; nf < 8; nf++) {
            float2 v0, v1;
            v0.x = c[mf][nf][0] + bb[nf].x;
            v0.y = c[mf][nf][1] + bb[nf].y;
            v1.x = c[mf][nf][2] + bb[nf].x;
            v1.y = c[mf][nf][3] + bb[nf].y;
            *reinterpret_cast<float2*>(out + m0 * OUT_F + n_col0 + nf * 8) = v0;
            *reinterpret_cast<float2*>(out + (m0 + 8) * OUT_F + n_col0 + nf * 8) = v1;
        }
    }
}

// ---------------- host ----------------
extern "C" void kernel_launch(void* const* d_in, const int* in_sizes, int n_in,
                              void* d_out, int out_size) {
    const float* x      = (const float*)d_in[0];
    const int*   wp     = (const int*)d_in[1];
    const float* scales = (const float*)d_in[2];
    const float* biases = (const float*)d_in[3];
    const float* bias   = (const float*)d_in[4];
    float* out = (float*)d_out;

    __half* xh = nullptr;
    __half* wh = nullptr;
    cudaGetSymbolAddress((void**)&xh, g_xh);
    cudaGetSymbolAddress((void**)&wh, g_wh);

    convert_x_kernel<<<(M_TOT * IN_F / 8) / 256, 256>>>((const float4*)x, (uint4*)xh);
    dequant_w_kernel<<<(OUT_F * PACKED) / 256, 256>>>(wp, scales, biases, wh);

    static bool attr_set = false;
    if (!attr_set) {
        cudaFuncSetAttribute(gemm_f16_kernel, cudaFuncAttributeMaxDynamicSharedMemorySize, SMEM_BYTES);
        attr_set = true;
    }
    gemm_f16_kernel<<<MT * NT, 256, SMEM_BYTES>>>(xh, wh, bias, out);
}

// round 3
// speedup vs baseline: 1.0463x; 1.0463x over previous
#include <cuda_runtime.h>
#include <cuda_fp16.h>
#include <cstdint>

// ---------------- problem dims ----------------
#define IN_F   4096
#define OUT_F  11008
#define M_TOT  8192
#define GROUPS 32
#define PACKED 512

// ---------------- GEMM tiling ----------------
#define BLOCK_M 128
#define BLOCK_N 256
#define BLOCK_K 64            // 64 halves = 128B rows
#define STAGES  3
#define NITER   (IN_F / BLOCK_K)   // 64
#define NT      (OUT_F / BLOCK_N)  // 43
#define MT      (M_TOT / BLOCK_M)  // 64

#define A_BYTES (BLOCK_M * 128)            // 16384
#define B_BYTES (BLOCK_N * 128)            // 32768
#define STAGE_BYTES (A_BYTES + B_BYTES)    // 49152
#define SMEM_BYTES (STAGES * STAGE_BYTES)  // 147456

// ---------------- scratch (device globals: allocation-free) ----------------
__device__ __align__(1024) __half g_xh[(size_t)M_TOT * IN_F];
__device__ __align__(1024) __half g_wh[(size_t)OUT_F * IN_F];

// ---------------- PTX helpers ----------------
__device__ __forceinline__ uint32_t smem_u32(const void* p) {
    uint32_t a;
    asm("{ .reg .u64 t; cvta.to.shared.u64 t, %1; cvt.u32.u64 %0, t; }" : "=r"(a) : "l"(p));
    return a;
}

#define CP_ASYNC_CG(smem, gptr) \
    asm volatile("cp.async.cg.shared.global [%0], [%1], 16;" :: "r"(smem), "l"(gptr) : "memory")
#define CP_COMMIT() asm volatile("cp.async.commit_group;" ::: "memory")
#define CP_WAIT1()  asm volatile("cp.async.wait_group 1;" ::: "memory")

#define LDSM_X4(R, addr) \
    asm volatile("ldmatrix.sync.aligned.m8n8.x4.shared.b16 {%0,%1,%2,%3}, [%4];" \
                 : "=r"((R)[0]), "=r"((R)[1]), "=r"((R)[2]), "=r"((R)[3]) : "r"(addr))

#define MMA16816(C, A, B) \
    asm volatile("mma.sync.aligned.m16n8k16.row.col.f32.f16.f16.f32 " \
                 "{%0,%1,%2,%3}, {%4,%5,%6,%7}, {%8,%9}, {%0,%1,%2,%3};" \
                 : "+f"((C)[0]), "+f"((C)[1]), "+f"((C)[2]), "+f"((C)[3]) \
                 : "r"((A)[0]), "r"((A)[1]), "r"((A)[2]), "r"((A)[3]), \
                   "r"((B)[0]), "r"((B)[1]))

// ---------------- kernel 1: x fp32 -> fp16 ----------------
__global__ void convert_x_kernel(const float4* __restrict__ x, uint4* __restrict__ out) {
    int i = blockIdx.x * blockDim.x + threadIdx.x;   // one uint4 = 8 halves
    float4 a = x[2 * i];
    float4 b = x[2 * i + 1];
    __half h[8];
    h[0] = __float2half(a.x); h[1] = __float2half(a.y);
    h[2] = __float2half(a.z); h[3] = __float2half(a.w);
    h[4] = __float2half(b.x); h[5] = __float2half(b.y);
    h[6] = __float2half(b.z); h[7] = __float2half(b.w);
    out[i] = *reinterpret_cast<uint4*>(h);
}

// ---------------- kernel 2: int4 dequant -> fp16 ----------------
__global__ void dequant_w_kernel(const int* __restrict__ wp, const float* __restrict__ scales,
                                 const float* __restrict__ biases, __half* __restrict__ out) {
    int idx = blockIdx.x * blockDim.x + threadIdx.x;  // packed-word index
    uint32_t w = (uint32_t)wp[idx];
    int o  = idx >> 9;          // / PACKED
    int wk = idx & 511;
    int g  = wk >> 4;           // 16 words per 128-feature group
    float s = scales[o * GROUPS + g];
    float b = biases[o * GROUPS + g];
    __half h[8];
#pragma unroll
    for (int j = 0; j < 8; j++) {
        float q = (float)((w >> (4 * j)) & 15u);
        h[j] = __float2half(fmaf(s, q, b));
    }
    *reinterpret_cast<uint4*>(out + (size_t)idx * 8) = *reinterpret_cast<uint4*>(h);
}

// ---------------- kernel 3: pipelined mma.sync fp16 GEMM ----------------
// CTA 128x256x64, 8 warps in 2(M) x 4(N), warp tile 64x64.
// smem rows are 128B (64 halves); swizzle: col16B ^= 16*(row&7).
// One __syncthreads per K-iter; register double-buffered LDSM fragments.
__global__ void __launch_bounds__(256, 1)
gemm_f16_kernel(const __half* __restrict__ Ag, const __half* __restrict__ Bg,
                const float* __restrict__ bias, float* __restrict__ out) {
    extern __shared__ char smem[];
    const uint32_t sbase = smem_u32(smem);

    const int tid = threadIdx.x;
    const int wid = tid >> 5;
    const int lid = tid & 31;

    const int nt = blockIdx.x % NT;
    const int mt = blockIdx.x / NT;

    const int warp_m = wid >> 2;          // 0..1
    const int warp_n = wid & 3;           // 0..3
    const int m_base = warp_m * 64;
    const int n_base = warp_n * 64;

    const __half* Agb = Ag + (size_t)mt * BLOCK_M * IN_F;
    const __half* Bgb = Bg + (size_t)nt * BLOCK_N * IN_F;

    // ---- ldmatrix per-thread precompute ----
    const int r  = lid & 7;      // row-within-8
    const int gq = lid >> 3;     // quad group 0..3
    const uint32_t xorv = r * 16;
    const uint32_t aRowOff = (uint32_t)(m_base + r + 8 * (gq & 1)) * 128;
    const uint32_t aKExtra = 16 * (gq >> 1);
    const uint32_t bRowOff = (uint32_t)(n_base + r) * 128 + (uint32_t)(gq >> 1) * 1024;
    const uint32_t bKExtra = 16 * (gq & 1);

    float c[4][8][4];
#pragma unroll
    for (int mf = 0; mf < 4; mf++)
#pragma unroll
        for (int nf = 0; nf < 8; nf++)
#pragma unroll
            for (int k = 0; k < 4; k++) c[mf][nf][k] = 0.f;

    // ---- async load of one stage ----
    auto load_stage = [&](int it, int stage) {
        const uint32_t sA = sbase + stage * STAGE_BYTES;
        const uint32_t sB = sA + A_BYTES;
        const int k0 = it * BLOCK_K;
#pragma unroll
        for (int k = 0; k < 4; k++) {           // A: 1024 chunks / 256 thr
            int i = tid + 256 * k;
            int row = i >> 3, cc = i & 7;
            const __half* gp = Agb + (size_t)row * IN_F + k0 + cc * 8;
            uint32_t sp = sA + row * 128 + ((cc * 16) ^ ((row & 7) * 16));
            CP_ASYNC_CG(sp, gp);
        }
#pragma unroll
        for (int k = 0; k < 8; k++) {           // B: 2048 chunks / 256 thr
            int i = tid + 256 * k;
            int row = i >> 3, cc = i & 7;
            const __half* gp = Bgb + (size_t)row * IN_F + k0 + cc * 8;
            uint32_t sp = sB + row * 128 + ((cc * 16) ^ ((row & 7) * 16));
            CP_ASYNC_CG(sp, gp);
        }
    };

    // prologue: stages 0,1
    load_stage(0, 0); CP_COMMIT();
    load_stage(1, 1); CP_COMMIT();

#pragma unroll 1
    for (int it = 0; it < NITER; it++) {
        CP_WAIT1();          // this thread's copies for stage it complete
        __syncthreads();     // all threads' copies visible; stage (it-1) fully consumed

        // refill the freed slot (held stage it-1)
        if (it + 2 < NITER) load_stage(it + 2, (it + 2) % STAGES);
        CP_COMMIT();

        const uint32_t sA = sbase + (it % STAGES) * STAGE_BYTES;
        const uint32_t sB = sA + A_BYTES;

        uint32_t a[2][4][4], b[2][4][4];
        auto ldfrags = [&](int buf, int ks) {
            const uint32_t ak = (uint32_t)(ks * 32);
#pragma unroll
            for (int mf = 0; mf < 4; mf++)
                LDSM_X4(a[buf][mf], sA + aRowOff + mf * 2048 + ((ak + aKExtra) ^ xorv));
#pragma unroll
            for (int jb = 0; jb < 4; jb++)
                LDSM_X4(b[buf][jb], sB + bRowOff + jb * 2048 + ((ak + bKExtra) ^ xorv));
        };

        ldfrags(0, 0);
#pragma unroll
        for (int ks = 0; ks < 4; ks++) {
            if (ks < 3) ldfrags((ks + 1) & 1, ks + 1);   // prefetch next frags
            const int cur = ks & 1;
#pragma unroll
            for (int mf = 0; mf < 4; mf++)
#pragma unroll
                for (int nf = 0; nf < 8; nf++)
                    MMA16816(c[mf][nf], a[cur][mf], &b[cur][nf >> 1][(nf & 1) * 2]);
        }
        // no trailing barrier: next iter's top barrier orders stage reuse
    }

    // ---- epilogue: add bias, store fp32 (regs only; no smem, no sync needed) ----
    const int m_lo = lid >> 2;          // 0..7
    const int n_lo = (lid & 3) * 2;     // 0,2,4,6
    const int n_col0 = nt * BLOCK_N + n_base + n_lo;

    float2 bb[8];
#pragma unroll
    for (int nf = 0; nf < 8; nf++) {
        bb[nf].x = __ldg(bias + n_col0 + nf * 8);
        bb[nf].y = __ldg(bias + n_col0 + nf * 8 + 1);
    }

#pragma unroll
    for (int mf = 0; mf < 4; mf++) {
        size_t m0 = (size_t)mt * BLOCK_M + m_base + mf * 16 + m_lo;
#pragma unroll
        for (int nf = 0; nf < 8; nf++) {
            float2 v0, v1;
            v0.x = c[mf][nf][0] + bb[nf].x;
            v0.y = c[mf][nf][1] + bb[nf].y;
            v1.x = c[mf][nf][2] + bb[nf].x;
            v1.y = c[mf][nf][3] + bb[nf].y;
            *reinterpret_cast<float2*>(out + m0 * OUT_F + n_col0 + nf * 8) = v0;
            *reinterpret_cast<float2*>(out + (m0 + 8) * OUT_F + n_col0 + nf * 8) = v1;
        }
    }
}

// ---------------- host ----------------
extern "C" void kernel_launch(void* const* d_in, const int* in_sizes, int n_in,
                              void* d_out, int out_size) {
    const float* x      = (const float*)d_in[0];
    const int*   wp     = (const int*)d_in[1];
    const float* scales = (const float*)d_in[2];
    const float* biases = (const float*)d_in[3];
    const float* bias   = (const float*)d_in[4];
    float* out = (float*)d_out;

    __half* xh = nullptr;
    __half* wh = nullptr;
    cudaGetSymbolAddress((void**)&xh, g_xh);
    cudaGetSymbolAddress((void**)&wh, g_wh);

    convert_x_kernel<<<(M_TOT * IN_F / 8) / 256, 256>>>((const float4*)x, (uint4*)xh);
    dequant_w_kernel<<<(OUT_F * PACKED) / 256, 256>>>(wp, scales, biases, wh);

    static bool attr_set = false;
    if (!attr_set) {
        cudaFuncSetAttribute(gemm_f16_kernel, cudaFuncAttributeMaxDynamicSharedMemorySize, SMEM_BYTES);
        attr_set = true;
    }
    gemm_f16_kernel<<<MT * NT, 256, SMEM_BYTES>>>(xh, wh, bias, out);
}

// round 4
// speedup vs baseline: 1.1659x; 1.1143x over previous
#include <cuda_runtime.h>
#include <cuda_fp16.h>
#include <cstdint>

// ---------------- problem dims ----------------
#define IN_F   4096
#define OUT_F  11008
#define M_TOT  8192
#define GROUPS 32
#define PACKED 512

// ---------------- GEMM tiling ----------------
#define BLOCK_M 128
#define BLOCK_N 128
#define BLOCK_K 64            // 64 halves = 128B rows
#define STAGES  3
#define NITER   (IN_F / BLOCK_K)   // 64
#define NT      (OUT_F / BLOCK_N)  // 86
#define MT      (M_TOT / BLOCK_M)  // 64

#define A_BYTES (BLOCK_M * 128)            // 16384
#define B_BYTES (BLOCK_N * 128)            // 16384
#define STAGE_BYTES (A_BYTES + B_BYTES)    // 32768
#define SMEM_BYTES (STAGES * STAGE_BYTES)  // 98304  (2 CTAs/SM -> 192K)

// ---------------- scratch (device globals: allocation-free) ----------------
__device__ __align__(1024) __half g_xh[(size_t)M_TOT * IN_F];
__device__ __align__(1024) __half g_wh[(size_t)OUT_F * IN_F];

// ---------------- PTX helpers ----------------
__device__ __forceinline__ uint32_t smem_u32(const void* p) {
    uint32_t a;
    asm("{ .reg .u64 t; cvta.to.shared.u64 t, %1; cvt.u32.u64 %0, t; }" : "=r"(a) : "l"(p));
    return a;
}

#define CP_ASYNC_CG(smem, gptr) \
    asm volatile("cp.async.cg.shared.global [%0], [%1], 16;" :: "r"(smem), "l"(gptr) : "memory")
#define CP_COMMIT() asm volatile("cp.async.commit_group;" ::: "memory")
#define CP_WAIT1()  asm volatile("cp.async.wait_group 1;" ::: "memory")

#define LDSM_X4(R, addr) \
    asm volatile("ldmatrix.sync.aligned.m8n8.x4.shared.b16 {%0,%1,%2,%3}, [%4];" \
                 : "=r"((R)[0]), "=r"((R)[1]), "=r"((R)[2]), "=r"((R)[3]) : "r"(addr))

#define MMA16816(C, A, B) \
    asm volatile("mma.sync.aligned.m16n8k16.row.col.f32.f16.f16.f32 " \
                 "{%0,%1,%2,%3}, {%4,%5,%6,%7}, {%8,%9}, {%0,%1,%2,%3};" \
                 : "+f"((C)[0]), "+f"((C)[1]), "+f"((C)[2]), "+f"((C)[3]) \
                 : "r"((A)[0]), "r"((A)[1]), "r"((A)[2]), "r"((A)[3]), \
                   "r"((B)[0]), "r"((B)[1]))

// ---------------- kernel 1: x fp32 -> fp16 ----------------
__global__ void convert_x_kernel(const float4* __restrict__ x, uint4* __restrict__ out) {
    int i = blockIdx.x * blockDim.x + threadIdx.x;   // one uint4 = 8 halves
    float4 a = x[2 * i];
    float4 b = x[2 * i + 1];
    __half h[8];
    h[0] = __float2half(a.x); h[1] = __float2half(a.y);
    h[2] = __float2half(a.z); h[3] = __float2half(a.w);
    h[4] = __float2half(b.x); h[5] = __float2half(b.y);
    h[6] = __float2half(b.z); h[7] = __float2half(b.w);
    out[i] = *reinterpret_cast<uint4*>(h);
}

// ---------------- kernel 2: int4 dequant -> fp16 ----------------
__global__ void dequant_w_kernel(const int* __restrict__ wp, const float* __restrict__ scales,
                                 const float* __restrict__ biases, __half* __restrict__ out) {
    int idx = blockIdx.x * blockDim.x + threadIdx.x;  // packed-word index
    uint32_t w = (uint32_t)wp[idx];
    int o  = idx >> 9;          // / PACKED
    int wk = idx & 511;
    int g  = wk >> 4;           // 16 words per 128-feature group
    float s = scales[o * GROUPS + g];
    float b = biases[o * GROUPS + g];
    __half h[8];
#pragma unroll
    for (int j = 0; j < 8; j++) {
        float q = (float)((w >> (4 * j)) & 15u);
        h[j] = __float2half(fmaf(s, q, b));
    }
    *reinterpret_cast<uint4*>(out + (size_t)idx * 8) = *reinterpret_cast<uint4*>(h);
}

// ---------------- kernel 3: pipelined mma.sync fp16 GEMM ----------------
// CTA 128x128x64, 4 warps in 2(M) x 2(N), warp tile 64x64, 2 CTAs/SM.
// smem rows are 128B (64 halves); swizzle: col16B ^= 16*(row&7).
__global__ void __launch_bounds__(128, 2)
gemm_f16_kernel(const __half* __restrict__ Ag, const __half* __restrict__ Bg,
                const float* __restrict__ bias, float* __restrict__ out) {
    extern __shared__ char smem[];
    const uint32_t sbase = smem_u32(smem);

    const int tid = threadIdx.x;
    const int wid = tid >> 5;
    const int lid = tid & 31;

    const int nt = blockIdx.x % NT;
    const int mt = blockIdx.x / NT;

    const int warp_m = wid >> 1;          // 0..1
    const int warp_n = wid & 1;           // 0..1
    const int m_base = warp_m * 64;
    const int n_base = warp_n * 64;

    const __half* Agb = Ag + (size_t)mt * BLOCK_M * IN_F;
    const __half* Bgb = Bg + (size_t)nt * BLOCK_N * IN_F;

    // ---- ldmatrix per-thread precompute ----
    const int r  = lid & 7;      // row-within-8
    const int gq = lid >> 3;     // quad group 0..3
    const uint32_t xorv = r * 16;
    const uint32_t aRowOff = (uint32_t)(m_base + r + 8 * (gq & 1)) * 128;
    const uint32_t aKExtra = 16 * (gq >> 1);
    const uint32_t bRowOff = (uint32_t)(n_base + r) * 128 + (uint32_t)(gq >> 1) * 1024;
    const uint32_t bKExtra = 16 * (gq & 1);

    float c[4][8][4];
#pragma unroll
    for (int mf = 0; mf < 4; mf++)
#pragma unroll
        for (int nf = 0; nf < 8; nf++)
#pragma unroll
            for (int k = 0; k < 4; k++) c[mf][nf][k] = 0.f;

    // ---- async load of one stage (A:1024 + B:1024 chunks, 128 threads) ----
    auto load_stage = [&](int it, int stage) {
        const uint32_t sA = sbase + stage * STAGE_BYTES;
        const uint32_t sB = sA + A_BYTES;
        const int k0 = it * BLOCK_K;
#pragma unroll
        for (int k = 0; k < 8; k++) {           // A
            int i = tid + 128 * k;
            int row = i >> 3, cc = i & 7;
            const __half* gp = Agb + (size_t)row * IN_F + k0 + cc * 8;
            uint32_t sp = sA + row * 128 + ((cc * 16) ^ ((row & 7) * 16));
            CP_ASYNC_CG(sp, gp);
        }
#pragma unroll
        for (int k = 0; k < 8; k++) {           // B
            int i = tid + 128 * k;
            int row = i >> 3, cc = i & 7;
            const __half* gp = Bgb + (size_t)row * IN_F + k0 + cc * 8;
            uint32_t sp = sB + row * 128 + ((cc * 16) ^ ((row & 7) * 16));
            CP_ASYNC_CG(sp, gp);
        }
    };

    // prologue: stages 0,1
    load_stage(0, 0); CP_COMMIT();
    load_stage(1, 1); CP_COMMIT();

#pragma unroll 1
    for (int it = 0; it < NITER; it++) {
        CP_WAIT1();          // this thread's copies for stage it complete
        __syncthreads();     // all threads' copies visible; stage (it-1) fully consumed

        // refill the freed slot (held stage it-1)
        if (it + 2 < NITER) load_stage(it + 2, (it + 2) % STAGES);
        CP_COMMIT();

        const uint32_t sA = sbase + (it % STAGES) * STAGE_BYTES;
        const uint32_t sB = sA + A_BYTES;

        uint32_t a[2][4][4], b[2][4][4];
        auto ldfrags = [&](int buf, int ks) {
            const uint32_t ak = (uint32_t)(ks * 32);
#pragma unroll
            for (int mf = 0; mf < 4; mf++)
                LDSM_X4(a[buf][mf], sA + aRowOff + mf * 2048 + ((ak + aKExtra) ^ xorv));
#pragma unroll
            for (int jb = 0; jb < 4; jb++)
                LDSM_X4(b[buf][jb], sB + bRowOff + jb * 2048 + ((ak + bKExtra) ^ xorv));
        };

        ldfrags(0, 0);
#pragma unroll
        for (int ks = 0; ks < 4; ks++) {
            if (ks < 3) ldfrags((ks + 1) & 1, ks + 1);   // prefetch next frags
            const int cur = ks & 1;
#pragma unroll
            for (int mf = 0; mf < 4; mf++)
#pragma unroll
                for (int nf = 0; nf < 8; nf++)
                    MMA16816(c[mf][nf], a[cur][mf], &b[cur][nf >> 1][(nf & 1) * 2]);
        }
        // no trailing barrier: next iter's top barrier orders stage reuse
    }

    // ---- epilogue: add bias, store fp32 (regs only) ----
    const int m_lo = lid >> 2;          // 0..7
    const int n_lo = (lid & 3) * 2;     // 0,2,4,6
    const int n_col0 = nt * BLOCK_N + n_base + n_lo;

    float2 bb[8];
#pragma unroll
    for (int nf = 0; nf < 8; nf++) {
        bb[nf].x = __ldg(bias + n_col0 + nf * 8);
        bb[nf].y = __ldg(bias + n_col0 + nf * 8 + 1);
    }

#pragma unroll
    for (int mf = 0; mf < 4; mf++) {
        size_t m0 = (size_t)mt * BLOCK_M + m_base + mf * 16 + m_lo;
#pragma unroll
        for (int nf = 0; nf < 8; nf++) {
            float2 v0, v1;
            v0.x = c[mf][nf][0] + bb[nf].x;
            v0.y = c[mf][nf][1] + bb[nf].y;
            v1.x = c[mf][nf][2] + bb[nf].x;
            v1.y = c[mf][nf][3] + bb[nf].y;
            *reinterpret_cast<float2*>(out + m0 * OUT_F + n_col0 + nf * 8) = v0;
            *reinterpret_cast<float2*>(out + (m0 + 8) * OUT_F + n_col0 + nf * 8) = v1;
        }
    }
}

// ---------------- host ----------------
extern "C" void kernel_launch(void* const* d_in, const int* in_sizes, int n_in,
                              void* d_out, int out_size) {
    const float* x      = (const float*)d_in[0];
    const int*   wp     = (const int*)d_in[1];
    const float* scales = (const float*)d_in[2];
    const float* biases = (const float*)d_in[3];
    const float* bias   = (const float*)d_in[4];
    float* out = (float*)d_out;

    __half* xh = nullptr;
    __half* wh = nullptr;
    cudaGetSymbolAddress((void**)&xh, g_xh);
    cudaGetSymbolAddress((void**)&wh, g_wh);

    convert_x_kernel<<<(M_TOT * IN_F / 8) / 256, 256>>>((const float4*)x, (uint4*)xh);
    dequant_w_kernel<<<(OUT_F * PACKED) / 256, 256>>>(wp, scales, biases, wh);

    static bool attr_set = false;
    if (!attr_set) {
        cudaFuncSetAttribute(gemm_f16_kernel, cudaFuncAttributeMaxDynamicSharedMemorySize, SMEM_BYTES);
        attr_set = true;
    }
    gemm_f16_kernel<<<MT * NT, 128, SMEM_BYTES>>>(xh, wh, bias, out);
}